// round 9
// baseline (speedup 1.0000x reference)
#include <cuda_runtime.h>
#include <cstdint>

#define B_SZ 16384
#define F_SZ 9000
#define BK   32
#define NCH  282             // ceil(9000/32); last chunk has 8 valid k
#define PL   4096            // plane bytes: 128 rows x 32B
#define A_H_OFF 0
#define A_L_OFF 4096
// W planes live in the same stage after A? No: stage = Ah|Al|Wh|Wl = 16KB -> 3 stages
#define WH_OFF 8192
#define WL_OFF 12288
#define STG_SZ 16384
#define SMEM_DYN (3 * STG_SZ)   // 49152 B exactly; no static smem in ft kernel

__device__ float g_scratch[B_SZ * 256];
__device__ int g_mode;
__device__ unsigned char g_wq[NCH * 2 * PL];   // per-chunk Wh|Wl s8 planes (SWZ layout)

__device__ __forceinline__ float screlu(float x) {
    x = fminf(fmaxf(x, 0.0f), 1.0f);
    return x * x;
}

__device__ __forceinline__ uint32_t smem_u32(const void* p) {
    uint32_t a;
    asm("{ .reg .u64 t; cvta.to.shared.u64 t, %1; cvt.u32.u64 %0, t; }" : "=r"(a) : "l"(p));
    return a;
}

// XOR swizzle for 32B rows: row r, 16B-half h -> conflict-free ldmatrix/STS
#define SWZ(r, h) ((uint32_t)((r) * 32 + (((h) ^ (((r) >> 2) & 1)) << 4)))

#define LDSM_X4(r, addr)                                                         \
    asm volatile("ldmatrix.sync.aligned.m8n8.x4.shared.b16 {%0,%1,%2,%3}, [%4];" \
                 : "=r"((r)[0]), "=r"((r)[1]), "=r"((r)[2]), "=r"((r)[3])        \
                 : "r"(addr))

#define IMMA(c, a, bb0, bb1)                                                     \
    asm volatile("mma.sync.aligned.m16n8k32.row.col.s32.u8.s8.s32 "              \
                 "{%0,%1,%2,%3}, {%4,%5,%6,%7}, {%8,%9}, {%0,%1,%2,%3};"         \
                 : "+r"((c)[0]), "+r"((c)[1]), "+r"((c)[2]), "+r"((c)[3])        \
                 : "r"((a)[0]), "r"((a)[1]), "r"((a)[2]), "r"((a)[3]),           \
                   "r"(bb0), "r"(bb1))

// 4 fp32 in [0,1) -> packed u8 hi + u8 lo (A = (hi*256+lo)/65535, exact u16)
__device__ __forceinline__ void quantA(float4 v, uint32_t& hi, uint32_t& lo) {
    int i0 = __float2int_rn(v.x * 65535.0f);
    int i1 = __float2int_rn(v.y * 65535.0f);
    int i2 = __float2int_rn(v.z * 65535.0f);
    int i3 = __float2int_rn(v.w * 65535.0f);
    uint32_t h01 = __byte_perm(i0, i1, 0x0051);
    uint32_t h23 = __byte_perm(i2, i3, 0x0051);
    hi = __byte_perm(h01, h23, 0x5410);
    uint32_t l01 = __byte_perm(i0, i1, 0x0040);
    uint32_t l23 = __byte_perm(i2, i3, 0x0040);
    lo = __byte_perm(l01, l23, 0x5410);
}

// ---------------------------------------------------------------------------
// Kernel 0: stm dtype sniff -> g_mode (0=int32, 1=uint8 bool, 2=float32)
// ---------------------------------------------------------------------------
__global__ void stm_detect_kernel(const unsigned char* __restrict__ p) {
    __shared__ int fFloat, fBool;
    if (threadIdx.x == 0) { fFloat = 0; fBool = 0; }
    __syncthreads();
    int lf = 0, lb = 0;
    for (int i = threadIdx.x; i < B_SZ; i += blockDim.x) {
        unsigned char v = p[i];
        if (v == 0x80u || v == 0x3fu) lf = 1;
        else if (v != 0u && (i & 3) != 0) lb = 1;
    }
    if (lf) atomicOr(&fFloat, 1);
    if (lb) atomicOr(&fBool, 1);
    __syncthreads();
    if (threadIdx.x == 0) g_mode = fFloat ? 2 : (fBool ? 1 : 0);
}

// ---------------------------------------------------------------------------
// Kernel 0b: pre-quantize ft_w into per-chunk s8 hi/lo planes (SWZ layout).
// W = (wh*256 + wl) / 262144   (scale 1024, then 256)
// thread t: row n = t>>1, 16B-half h = t&1 -> 16 k-values.
// ---------------------------------------------------------------------------
__global__ void wquant_kernel(const float* __restrict__ ftw) {
    const int c = blockIdx.x;
    const int t = threadIdx.x;
    const int n = t >> 1, h = t & 1;
    const int kb = c * BK + h * 16;
    const float* src = ftw + (size_t)n * F_SZ;

    uint32_t hw[4], lw[4];
#pragma unroll
    for (int j = 0; j < 4; j++) {
        float4 v = make_float4(0, 0, 0, 0);
        if (kb + j * 4 + 4 <= F_SZ) v = *(const float4*)(src + kb + j * 4);
        int wh[4], wl[4];
        const float* f = &v.x;
#pragma unroll
        for (int e = 0; e < 4; e++) {
            float s = f[e] * 1024.0f;
            int a = __float2int_rn(s);
            a = max(-127, min(127, a));
            int b = __float2int_rn((s - (float)a) * 256.0f);
            b = max(-127, min(127, b));
            wh[e] = a; wl[e] = b;
        }
        hw[j] = (wh[0] & 0xff) | ((wh[1] & 0xff) << 8) | ((wh[2] & 0xff) << 16) | ((wh[3] & 0xff) << 24);
        lw[j] = (wl[0] & 0xff) | ((wl[1] & 0xff) << 8) | ((wl[2] & 0xff) << 16) | ((wl[3] & 0xff) << 24);
    }
    unsigned char* dst = g_wq + (size_t)(c * 2) * PL + SWZ(n, h);
    *(uint4*)dst        = make_uint4(hw[0], hw[1], hw[2], hw[3]);
    *(uint4*)(dst + PL) = make_uint4(lw[0], lw[1], lw[2], lw[3]);
}

// ---------------------------------------------------------------------------
// Kernel 1: int8 IMMA FT GEMM, 3 terms (hi*wh | hi*wl + lo*wh), k32 chunks.
// 256 thr, 8 warps (2m x 4n), warp tile 64x32, 3-stage cp.async pipeline.
// ---------------------------------------------------------------------------
__global__ __launch_bounds__(256, 1)
void ft_imma_kernel(const float* __restrict__ white,
                    const float* __restrict__ black,
                    const float* __restrict__ ftb) {
    extern __shared__ char smc[];
    const int t = threadIdx.x;
    const int lane = t & 31, wid = t >> 5;
    const int wm = wid >> 2, wn = wid & 3;
    const int color = blockIdx.y;
    const int row0 = blockIdx.x * 128;
    const float* __restrict__ A = color ? black : white;
    const uint32_t base = smem_u32(smc);

    // loader mapping: thread t -> A row t>>1, 16B-half t&1 (16 k-values)
    const int lrow = t >> 1, lh = t & 1;
    const float* aRow = A + (size_t)(row0 + lrow) * F_SZ + lh * 16;
    const uint32_t aDst = SWZ(lrow, lh);
    const unsigned char* wSrc = g_wq + t * 16;   // linear 16B piece of 4KB plane

    float4 aReg[4];

    auto loadA = [&](int ch) {
        const int kb = ch * BK + lh * 16;
#pragma unroll
        for (int j = 0; j < 4; j++) {
            if (kb + j * 4 + 4 <= F_SZ)
                aReg[j] = *(const float4*)(aRow + ch * BK + j * 4);
            else
                aReg[j] = make_float4(0, 0, 0, 0);
        }
    };
    auto cpW = [&](int ch, int stg) {
        const uint32_t sb = base + stg * STG_SZ;
        const unsigned char* s = wSrc + (size_t)(ch * 2) * PL;
        asm volatile("cp.async.cg.shared.global [%0], [%1], 16;"
                     :: "r"(sb + WH_OFF + (uint32_t)(t * 16)), "l"(s) : "memory");
        asm volatile("cp.async.cg.shared.global [%0], [%1], 16;"
                     :: "r"(sb + WL_OFF + (uint32_t)(t * 16)), "l"(s + PL) : "memory");
    };
    auto convA = [&](int stg) {
        uint32_t hi[4], lo[4];
#pragma unroll
        for (int j = 0; j < 4; j++) quantA(aReg[j], hi[j], lo[j]);
        char* p = smc + stg * STG_SZ;
        *(uint4*)(p + A_H_OFF + aDst) = make_uint4(hi[0], hi[1], hi[2], hi[3]);
        *(uint4*)(p + A_L_OFF + aDst) = make_uint4(lo[0], lo[1], lo[2], lo[3]);
    };

    // ldmatrix lane offsets
    const uint32_t offA = SWZ(wm * 64 + (lane & 15), lane >> 4);
    const uint32_t offB = SWZ(wn * 32 + ((lane >> 4) << 3) + (lane & 7), (lane >> 3) & 1);

    int acc1[4][4][4], acc2[4][4][4];
#pragma unroll
    for (int i = 0; i < 4; i++)
#pragma unroll
        for (int j = 0; j < 4; j++)
#pragma unroll
            for (int q = 0; q < 4; q++) { acc1[i][j][q] = 0; acc2[i][j][q] = 0; }

    // ---- prologue: chunks 0,1 -> stages 0,1
    cpW(0, 0);
    asm volatile("cp.async.commit_group;" ::: "memory");
    loadA(0); convA(0);
    cpW(1, 1);
    asm volatile("cp.async.commit_group;" ::: "memory");
    loadA(1); convA(1);
    asm volatile("cp.async.wait_group 0;" ::: "memory");
    __syncthreads();

    int stg = 0, stg2 = 2;
    for (int c = 0; c < NCH; ++c) {
        const bool more = (c + 2) < NCH;
        if (more) { loadA(c + 2); cpW(c + 2, stg2); }
        asm volatile("cp.async.commit_group;" ::: "memory");

        // ---- MMA on stage stg
        {
            const uint32_t sb = base + stg * STG_SZ;
            uint32_t ah[4][4], bh[2][4], bl[2][4];
#pragma unroll
            for (int mi = 0; mi < 4; mi++) LDSM_X4(ah[mi], sb + A_H_OFF + offA + mi * 512);
            LDSM_X4(bh[0], sb + WH_OFF + offB);
            LDSM_X4(bh[1], sb + WH_OFF + offB + 512);
            // T1: hi * wh -> acc1
#pragma unroll
            for (int mi = 0; mi < 4; mi++)
#pragma unroll
                for (int p = 0; p < 2; p++) {
                    IMMA(acc1[mi][p * 2 + 0], ah[mi], bh[p][0], bh[p][1]);
                    IMMA(acc1[mi][p * 2 + 1], ah[mi], bh[p][2], bh[p][3]);
                }
            LDSM_X4(bl[0], sb + WL_OFF + offB);
            LDSM_X4(bl[1], sb + WL_OFF + offB + 512);
            // T2a: hi * wl -> acc2
#pragma unroll
            for (int mi = 0; mi < 4; mi++)
#pragma unroll
                for (int p = 0; p < 2; p++) {
                    IMMA(acc2[mi][p * 2 + 0], ah[mi], bl[p][0], bl[p][1]);
                    IMMA(acc2[mi][p * 2 + 1], ah[mi], bl[p][2], bl[p][3]);
                }
            // T2b: lo * wh -> acc2 (reuse ah regs for lo frags)
#pragma unroll
            for (int mi = 0; mi < 4; mi++) LDSM_X4(ah[mi], sb + A_L_OFF + offA + mi * 512);
#pragma unroll
            for (int mi = 0; mi < 4; mi++)
#pragma unroll
                for (int p = 0; p < 2; p++) {
                    IMMA(acc2[mi][p * 2 + 0], ah[mi], bh[p][0], bh[p][1]);
                    IMMA(acc2[mi][p * 2 + 1], ah[mi], bh[p][2], bh[p][3]);
                }
        }

        if (more) convA(stg2);
        asm volatile("cp.async.wait_group 1;" ::: "memory");
        __syncthreads();

        if (++stg == 3) stg = 0;
        if (++stg2 == 3) stg2 = 0;
    }

    // ---- epilogue: combine limbs (double, exact), +bias, screlu -> scratch
    const double INV = 1.0 / (65535.0 * 262144.0);
#pragma unroll
    for (int mi = 0; mi < 4; mi++) {
#pragma unroll
        for (int hf = 0; hf < 2; hf++) {
            const int m = wm * 64 + mi * 16 + (lane >> 2) + hf * 8;
            float* dstRow = g_scratch + (size_t)(row0 + m) * 256 + color * 128;
#pragma unroll
            for (int ni = 0; ni < 4; ni++) {
                const int n = wn * 32 + ni * 8 + (lane & 3) * 2;
                float2 bias = *(const float2*)(ftb + n);
                double s0 = ((double)acc1[mi][ni][hf * 2 + 0] * 65536.0 +
                             (double)acc2[mi][ni][hf * 2 + 0] * 256.0) * INV;
                double s1 = ((double)acc1[mi][ni][hf * 2 + 1] * 65536.0 +
                             (double)acc2[mi][ni][hf * 2 + 1] * 256.0) * INV;
                float2 o;
                o.x = screlu((float)s0 + bias.x);
                o.y = screlu((float)s1 + bias.y);
                *(float2*)(dstRow + n) = o;
            }
        }
    }
}

// ---------------------------------------------------------------------------
// Kernel 2: tail MLP. 512 blocks x 8 warps x 4 rows/warp.
// ---------------------------------------------------------------------------
__global__ __launch_bounds__(256)
void tail_kernel(const unsigned char* __restrict__ stm,
                 const float* __restrict__ l1w, const float* __restrict__ l1b,
                 const float* __restrict__ l2w, const float* __restrict__ l2b,
                 const float* __restrict__ outw, const float* __restrict__ outb,
                 float* __restrict__ out) {
    __shared__ float l1w_s[32][260];
    __shared__ float xs[8][256];
    __shared__ float x1s[8][32];
    __shared__ float l2wT[32 * 32];
    __shared__ float l1b_s[32], l2b_s[32], outw_s[32];

    const int t = threadIdx.x;
    for (int idx = t; idx < 32 * 256; idx += 256) {
        int i = idx >> 8, k = idx & 255;
        l1w_s[i][k] = l1w[idx];
    }
    for (int idx = t; idx < 32 * 32; idx += 256) {
        int i = idx >> 5, j = idx & 31;
        l2wT[j * 32 + i] = l2w[idx];
    }
    if (t < 32) {
        l1b_s[t] = l1b[t];
        l2b_s[t] = l2b[t];
        outw_s[t] = outw[t];
    }
    __syncthreads();

    const int w = t >> 5;
    const int lane = t & 31;
    const int mode = g_mode;

#pragma unroll 1
    for (int rr = 0; rr < 4; ++rr) {
        const int r = blockIdx.x * 32 + w * 4 + rr;
        bool s;
        if (mode == 2)      s = (((const float*)(const void*)stm)[r] != 0.0f);
        else if (mode == 1) s = (stm[r] != 0u);
        else                s = (((const int*)(const void*)stm)[r] != 0);
        const int rot = s ? 128 : 0;

        const float* src = g_scratch + (size_t)r * 256;
#pragma unroll
        for (int p = 0; p < 2; p++) {
            const int fi = ((lane + 32 * p) * 4 + rot) & 255;
            *(float4*)&xs[w][(lane + 32 * p) * 4] = *(const float4*)(src + fi);
        }
        __syncwarp();

        float o1 = l1b_s[lane];
#pragma unroll 8
        for (int k4 = 0; k4 < 64; k4++) {
            float4 wv = *(const float4*)&l1w_s[lane][k4 * 4];
            float4 xv = *(const float4*)&xs[w][k4 * 4];
            o1 += wv.x * xv.x + wv.y * xv.y + wv.z * xv.z + wv.w * xv.w;
        }
        x1s[w][lane] = screlu(o1);
        __syncwarp();

        float o2 = l2b_s[lane];
#pragma unroll
        for (int j = 0; j < 32; j++)
            o2 += l2wT[j * 32 + lane] * x1s[w][j];

        float v = screlu(o2) * outw_s[lane];
#pragma unroll
        for (int off = 16; off; off >>= 1)
            v += __shfl_xor_sync(0xffffffffu, v, off);
        if (lane == 0) out[r] = v + outb[0];
        __syncwarp();
    }
}

// ---------------------------------------------------------------------------
extern "C" void kernel_launch(void* const* d_in, const int* in_sizes, int n_in,
                              void* d_out, int out_size) {
    const float* white = (const float*)d_in[0];
    const float* black = (const float*)d_in[1];
    const unsigned char* stm = (const unsigned char*)d_in[2];
    const float* ftw  = (const float*)d_in[3];
    const float* ftb  = (const float*)d_in[4];
    const float* l1w  = (const float*)d_in[5];
    const float* l1b  = (const float*)d_in[6];
    const float* l2w  = (const float*)d_in[7];
    const float* l2b  = (const float*)d_in[8];
    const float* outw = (const float*)d_in[9];
    const float* outb = (const float*)d_in[10];
    float* out = (float*)d_out;

    stm_detect_kernel<<<1, 1024>>>(stm);
    wquant_kernel<<<NCH, 256>>>(ftw);
    ft_imma_kernel<<<dim3(B_SZ / 128, 2), 256, SMEM_DYN>>>(white, black, ftb);
    tail_kernel<<<B_SZ / 32, 256>>>(stm, l1w, l1b, l2w, l2b, outw, outb, out);
}

// round 10
// speedup vs baseline: 3.8730x; 3.8730x over previous
#include <cuda_runtime.h>
#include <cuda_fp16.h>
#include <cstdint>

#define B_SZ 16384
#define F_SZ 9000
#define BK   32
#define NCH  282             // ceil(9000/32); last chunk 8 valid k
#define PL   4096            // sub-plane bytes: 128 rows x 32B
// stage layout: A_s0 | A_s1 | Wh_s0 | Wh_s1 | Wl_s0 | Wl_s1
#define W_OFF   8192
#define WCHUNK  16384        // W bytes per chunk in g_wbf (4 planes)
#define STG_SZ  24576
#define SMEM_DYN (2 * STG_SZ)   // 49152 B exactly; no static smem in ft kernel

__device__ float g_scratch[B_SZ * 256];
__device__ int g_mode;
__device__ unsigned char g_wbf[NCH * WCHUNK];  // per-chunk [Wh_s0|Wh_s1|Wl_s0|Wl_s1]

__device__ __forceinline__ float screlu(float x) {
    x = fminf(fmaxf(x, 0.0f), 1.0f);
    return x * x;
}

__device__ __forceinline__ uint32_t smem_u32(const void* p) {
    uint32_t a;
    asm("{ .reg .u64 t; cvta.to.shared.u64 t, %1; cvt.u32.u64 %0, t; }" : "=r"(a) : "l"(p));
    return a;
}

// XOR swizzle for 32B rows: row r, 16B-half h -> conflict-free ldmatrix/STS
#define SWZ(r, h) ((uint32_t)((r) * 32 + (((h) ^ (((r) >> 2) & 1)) << 4)))

__device__ __forceinline__ uint32_t h2u(__half2 h) {
    uint32_t u;
    *(__half2*)&u = h;
    return u;
}
__device__ __forceinline__ uint32_t cvtH2(float x0, float x1) {
    return h2u(__floats2half2_rn(x0, x1));
}
__device__ __forceinline__ void splitH2(float x0, float x1, uint32_t& h, uint32_t& l) {
    __half2 hh = __floats2half2_rn(x0, x1);
    float r0 = x0 - __low2float(hh);
    float r1 = x1 - __high2float(hh);
    h = h2u(hh);
    l = h2u(__floats2half2_rn(r0, r1));
}

#define LDSM_X4(r, addr)                                                         \
    asm volatile("ldmatrix.sync.aligned.m8n8.x4.shared.b16 {%0,%1,%2,%3}, [%4];" \
                 : "=r"((r)[0]), "=r"((r)[1]), "=r"((r)[2]), "=r"((r)[3])        \
                 : "r"(addr))

#define MMA16816(c, a, bb0, bb1)                                                 \
    asm volatile("mma.sync.aligned.m16n8k16.row.col.f32.f16.f16.f32 "            \
                 "{%0,%1,%2,%3}, {%4,%5,%6,%7}, {%8,%9}, {%0,%1,%2,%3};"         \
                 : "+f"((c)[0]), "+f"((c)[1]), "+f"((c)[2]), "+f"((c)[3])        \
                 : "r"((a)[0]), "r"((a)[1]), "r"((a)[2]), "r"((a)[3]),           \
                   "r"(bb0), "r"(bb1))

// ---------------------------------------------------------------------------
// Kernel 0: stm dtype sniff -> g_mode
// ---------------------------------------------------------------------------
__global__ void stm_detect_kernel(const unsigned char* __restrict__ p) {
    __shared__ int fFloat, fBool;
    if (threadIdx.x == 0) { fFloat = 0; fBool = 0; }
    __syncthreads();
    int lf = 0, lb = 0;
    for (int i = threadIdx.x; i < B_SZ; i += blockDim.x) {
        unsigned char v = p[i];
        if (v == 0x80u || v == 0x3fu) lf = 1;
        else if (v != 0u && (i & 3) != 0) lb = 1;
    }
    if (lf) atomicOr(&fFloat, 1);
    if (lb) atomicOr(&fBool, 1);
    __syncthreads();
    if (threadIdx.x == 0) g_mode = fFloat ? 2 : (fBool ? 1 : 0);
}

// ---------------------------------------------------------------------------
// Kernel 0b: pre-split ft_w into per-chunk fp16 hi/lo sub-planes (SWZ layout).
// thread t: row n = t>>1, half lh = t&1; covers k {s*16 + lh*8 .. +8} for s=0,1
// ---------------------------------------------------------------------------
__global__ void wprep_kernel(const float* __restrict__ ftw) {
    const int c = blockIdx.x;
    const int t = threadIdx.x;
    const int n = t >> 1, lh = t & 1;
    const float* src = ftw + (size_t)n * F_SZ;
    unsigned char* dstC = g_wbf + (size_t)c * WCHUNK;

#pragma unroll
    for (int s = 0; s < 2; s++) {
        const int kb = c * BK + s * 16 + lh * 8;
        float4 v0 = make_float4(0, 0, 0, 0), v1 = v0;
        if (kb + 4 <= F_SZ) v0 = *(const float4*)(src + kb);
        if (kb + 8 <= F_SZ) v1 = *(const float4*)(src + kb + 4);
        uint32_t h0, l0, h1, l1, h2, l2, h3, l3;
        splitH2(v0.x, v0.y, h0, l0);
        splitH2(v0.z, v0.w, h1, l1);
        splitH2(v1.x, v1.y, h2, l2);
        splitH2(v1.z, v1.w, h3, l3);
        unsigned char* d = dstC + s * PL + SWZ(n, lh);
        *(uint4*)d              = make_uint4(h0, h1, h2, h3);   // Wh_s
        *(uint4*)(d + 2 * PL)   = make_uint4(l0, l1, l2, l3);   // Wl_s
    }
}

// ---------------------------------------------------------------------------
// Kernel 1: fp16 2-term FT GEMM, BK=32 (two k16 sub-steps per chunk).
// 256 thr, 8 warps (2m x 4n), 64x32 warp tiles, 2-stage cp.async pipeline.
// ---------------------------------------------------------------------------
__global__ __launch_bounds__(256, 2)
void ft_mma_kernel(const float* __restrict__ white,
                   const float* __restrict__ black,
                   const float* __restrict__ ftb) {
    extern __shared__ char smc[];
    const int t = threadIdx.x;
    const int lane = t & 31, wid = t >> 5;
    const int wm = wid >> 2, wn = wid & 3;
    const int color = blockIdx.y;
    const int row0 = blockIdx.x * 128;
    const float* __restrict__ A = color ? black : white;
    const uint32_t base = smem_u32(smc);

    // loader mapping: thread t -> row t>>1, 16B-half lh = t&1
    const int lrow = t >> 1, lh = t & 1;
    const float* aRow = A + (size_t)(row0 + lrow) * F_SZ;
    const uint32_t aDst = SWZ(lrow, lh);
    const unsigned char* wSrc = g_wbf + t * 16;

    float4 aq[2];

    auto ldA = [&](int ch, int s) {
        const int kb = ch * BK + s * 16 + lh * 8;
        aq[0] = (kb + 4 <= F_SZ) ? *(const float4*)(aRow + kb) : make_float4(0, 0, 0, 0);
        aq[1] = (kb + 8 <= F_SZ) ? *(const float4*)(aRow + kb + 4) : make_float4(0, 0, 0, 0);
    };
    auto stsA = [&](int stg, int s) {
        uint4 v;
        v.x = cvtH2(aq[0].x, aq[0].y);
        v.y = cvtH2(aq[0].z, aq[0].w);
        v.z = cvtH2(aq[1].x, aq[1].y);
        v.w = cvtH2(aq[1].z, aq[1].w);
        *(uint4*)(smc + stg * STG_SZ + s * PL + aDst) = v;
    };
    auto cpW = [&](int ch, int stg) {
        const uint32_t db = base + stg * STG_SZ + W_OFF + (uint32_t)(t * 16);
        const unsigned char* s = wSrc + (size_t)ch * WCHUNK;
#pragma unroll
        for (int p = 0; p < 4; p++)
            asm volatile("cp.async.cg.shared.global [%0], [%1], 16;"
                         :: "r"(db + p * PL), "l"(s + p * PL) : "memory");
    };

    // ldmatrix lane offsets
    const uint32_t offA = SWZ(wm * 64 + (lane & 15), lane >> 4);
    const uint32_t offB = SWZ(wn * 32 + ((lane >> 4) << 3) + (lane & 7), (lane >> 3) & 1);

    float acc[4][4][4];
#pragma unroll
    for (int i = 0; i < 4; i++)
#pragma unroll
        for (int j = 0; j < 4; j++)
#pragma unroll
            for (int q = 0; q < 4; q++) acc[i][j][q] = 0.0f;

    // ---- prologue: chunk 0 -> stage 0
    cpW(0, 0);
    asm volatile("cp.async.commit_group;" ::: "memory");
    ldA(0, 0); stsA(0, 0);
    ldA(0, 1); stsA(0, 1);
    asm volatile("cp.async.wait_group 0;" ::: "memory");
    __syncthreads();

    for (int c = 0; c < NCH; ++c) {
        const int cur = c & 1, nxt = cur ^ 1;
        const bool more = (c + 1) < NCH;

        if (more) { ldA(c + 1, 0); cpW(c + 1, nxt); }
        asm volatile("cp.async.commit_group;" ::: "memory");

        const uint32_t sb = base + cur * STG_SZ;
#pragma unroll
        for (int s = 0; s < 2; s++) {
            const uint32_t aPl = sb + s * PL;
            const uint32_t wPl = sb + W_OFF + s * PL;
            uint32_t a[4][4], bh[2][4], bl[2][4];
#pragma unroll
            for (int mi = 0; mi < 4; mi++) LDSM_X4(a[mi], aPl + offA + mi * 512);
            LDSM_X4(bh[0], wPl + offB);
            LDSM_X4(bh[1], wPl + offB + 512);
#pragma unroll
            for (int mi = 0; mi < 4; mi++)
#pragma unroll
                for (int ni = 0; ni < 4; ni++) {
                    const int q = ni >> 1, r = (ni & 1) * 2;
                    MMA16816(acc[mi][ni], a[mi], bh[q][r], bh[q][r + 1]);
                }
            LDSM_X4(bl[0], wPl + 2 * PL + offB);
            LDSM_X4(bl[1], wPl + 2 * PL + offB + 512);
#pragma unroll
            for (int mi = 0; mi < 4; mi++)
#pragma unroll
                for (int ni = 0; ni < 4; ni++) {
                    const int q = ni >> 1, r = (ni & 1) * 2;
                    MMA16816(acc[mi][ni], a[mi], bl[q][r], bl[q][r + 1]);
                }
            // interleave next-chunk A prep between the two MMA sub-steps
            if (s == 0 && more) { stsA(nxt, 0); ldA(c + 1, 1); }
        }
        if (more) stsA(nxt, 1);

        asm volatile("cp.async.wait_group 0;" ::: "memory");
        __syncthreads();
    }

    // ---- epilogue: +bias (gmem, L1-cached), screlu -> g_scratch
    float2 bias[4];
#pragma unroll
    for (int ni = 0; ni < 4; ni++) {
        const int n = wn * 32 + ni * 8 + (lane & 3) * 2;
        bias[ni] = *(const float2*)(ftb + n);
    }
#pragma unroll
    for (int mi = 0; mi < 4; mi++) {
#pragma unroll
        for (int hf = 0; hf < 2; hf++) {
            const int m = wm * 64 + mi * 16 + (lane >> 2) + hf * 8;
            float* dstRow = g_scratch + (size_t)(row0 + m) * 256 + color * 128;
#pragma unroll
            for (int ni = 0; ni < 4; ni++) {
                const int n = wn * 32 + ni * 8 + (lane & 3) * 2;
                float2 o;
                o.x = screlu(acc[mi][ni][hf * 2 + 0] + bias[ni].x);
                o.y = screlu(acc[mi][ni][hf * 2 + 1] + bias[ni].y);
                *(float2*)(dstRow + n) = o;
            }
        }
    }
}

// ---------------------------------------------------------------------------
// Kernel 2: tail MLP. 512 blocks x 8 warps x 4 rows/warp.
// ---------------------------------------------------------------------------
__global__ __launch_bounds__(256)
void tail_kernel(const unsigned char* __restrict__ stm,
                 const float* __restrict__ l1w, const float* __restrict__ l1b,
                 const float* __restrict__ l2w, const float* __restrict__ l2b,
                 const float* __restrict__ outw, const float* __restrict__ outb,
                 float* __restrict__ out) {
    __shared__ float l1w_s[32][260];
    __shared__ float xs[8][256];
    __shared__ float x1s[8][32];
    __shared__ float l2wT[32 * 32];
    __shared__ float l1b_s[32], l2b_s[32], outw_s[32];

    const int t = threadIdx.x;
    for (int idx = t; idx < 32 * 256; idx += 256) {
        int i = idx >> 8, k = idx & 255;
        l1w_s[i][k] = l1w[idx];
    }
    for (int idx = t; idx < 32 * 32; idx += 256) {
        int i = idx >> 5, j = idx & 31;
        l2wT[j * 32 + i] = l2w[idx];
    }
    if (t < 32) {
        l1b_s[t] = l1b[t];
        l2b_s[t] = l2b[t];
        outw_s[t] = outw[t];
    }
    __syncthreads();

    const int w = t >> 5;
    const int lane = t & 31;
    const int mode = g_mode;

#pragma unroll 1
    for (int rr = 0; rr < 4; ++rr) {
        const int r = blockIdx.x * 32 + w * 4 + rr;
        bool s;
        if (mode == 2)      s = (((const float*)(const void*)stm)[r] != 0.0f);
        else if (mode == 1) s = (stm[r] != 0u);
        else                s = (((const int*)(const void*)stm)[r] != 0);
        const int rot = s ? 128 : 0;

        const float* src = g_scratch + (size_t)r * 256;
#pragma unroll
        for (int p = 0; p < 2; p++) {
            const int fi = ((lane + 32 * p) * 4 + rot) & 255;
            *(float4*)&xs[w][(lane + 32 * p) * 4] = *(const float4*)(src + fi);
        }
        __syncwarp();

        float o1 = l1b_s[lane];
#pragma unroll 8
        for (int k4 = 0; k4 < 64; k4++) {
            float4 wv = *(const float4*)&l1w_s[lane][k4 * 4];
            float4 xv = *(const float4*)&xs[w][k4 * 4];
            o1 += wv.x * xv.x + wv.y * xv.y + wv.z * xv.z + wv.w * xv.w;
        }
        x1s[w][lane] = screlu(o1);
        __syncwarp();

        float o2 = l2b_s[lane];
#pragma unroll
        for (int j = 0; j < 32; j++)
            o2 += l2wT[j * 32 + lane] * x1s[w][j];

        float v = screlu(o2) * outw_s[lane];
#pragma unroll
        for (int off = 16; off; off >>= 1)
            v += __shfl_xor_sync(0xffffffffu, v, off);
        if (lane == 0) out[r] = v + outb[0];
        __syncwarp();
    }
}

// ---------------------------------------------------------------------------
extern "C" void kernel_launch(void* const* d_in, const int* in_sizes, int n_in,
                              void* d_out, int out_size) {
    const float* white = (const float*)d_in[0];
    const float* black = (const float*)d_in[1];
    const unsigned char* stm = (const unsigned char*)d_in[2];
    const float* ftw  = (const float*)d_in[3];
    const float* ftb  = (const float*)d_in[4];
    const float* l1w  = (const float*)d_in[5];
    const float* l1b  = (const float*)d_in[6];
    const float* l2w  = (const float*)d_in[7];
    const float* l2b  = (const float*)d_in[8];
    const float* outw = (const float*)d_in[9];
    const float* outb = (const float*)d_in[10];
    float* out = (float*)d_out;

    stm_detect_kernel<<<1, 1024>>>(stm);
    wprep_kernel<<<NCH, 256>>>(ftw);
    ft_mma_kernel<<<dim3(B_SZ / 128, 2), 256, SMEM_DYN>>>(white, black, ftb);
    tail_kernel<<<B_SZ / 32, 256>>>(stm, l1w, l1b, l2w, l2b, outw, outb, out);
}

// round 11
// speedup vs baseline: 3.9821x; 1.0282x over previous
#include <cuda_runtime.h>
#include <cuda_fp16.h>
#include <cstdint>

#define B_SZ 16384
#define F_SZ 9000
#define BK   32
#define NCH  282             // ceil(9000/32); last chunk 8 valid k
#define PL   4096            // sub-plane bytes: 128 rows x 32B
// stage layout: A_s0 | A_s1 | W_s0 | W_s1
#define W_OFF   8192
#define WCHUNK  8192         // W bytes per chunk in g_wh (2 planes)
#define STG_SZ  16384
#define SMEM_DYN (3 * STG_SZ)   // 49152 B exactly; no static smem in ft kernel

__device__ float g_scratch[B_SZ * 256];
__device__ int g_mode;
__device__ float g_wsum[128];
__device__ unsigned char g_wh[NCH * WCHUNK];   // per-chunk [W_s0|W_s1] fp16, SWZ layout

__device__ __forceinline__ float screlu(float x) {
    x = fminf(fmaxf(x, 0.0f), 1.0f);
    return x * x;
}

__device__ __forceinline__ uint32_t smem_u32(const void* p) {
    uint32_t a;
    asm("{ .reg .u64 t; cvta.to.shared.u64 t, %1; cvt.u32.u64 %0, t; }" : "=r"(a) : "l"(p));
    return a;
}

// XOR swizzle for 32B rows: row r, 16B-half h -> conflict-free ldmatrix/STS
#define SWZ(r, h) ((uint32_t)((r) * 32 + (((h) ^ (((r) >> 2) & 1)) << 4)))

__device__ __forceinline__ uint32_t h2u(__half2 h) {
    uint32_t u;
    *(__half2*)&u = h;
    return u;
}
__device__ __forceinline__ uint32_t cvtH2(float x0, float x1) {
    return h2u(__floats2half2_rn(x0, x1));
}

#define LDSM_X4(r, addr)                                                         \
    asm volatile("ldmatrix.sync.aligned.m8n8.x4.shared.b16 {%0,%1,%2,%3}, [%4];" \
                 : "=r"((r)[0]), "=r"((r)[1]), "=r"((r)[2]), "=r"((r)[3])        \
                 : "r"(addr))

#define MMA16816(c, a, bb0, bb1)                                                 \
    asm volatile("mma.sync.aligned.m16n8k16.row.col.f32.f16.f16.f32 "            \
                 "{%0,%1,%2,%3}, {%4,%5,%6,%7}, {%8,%9}, {%0,%1,%2,%3};"         \
                 : "+f"((c)[0]), "+f"((c)[1]), "+f"((c)[2]), "+f"((c)[3])        \
                 : "r"((a)[0]), "r"((a)[1]), "r"((a)[2]), "r"((a)[3]),           \
                   "r"(bb0), "r"(bb1))

// ---------------------------------------------------------------------------
// Kernel 0: W prep (fp16 1-limb, SWZ layout) + stm dtype sniff (extra block).
// blocks [0, NCH): chunk conversion; block NCH: stm detect -> g_mode.
// ---------------------------------------------------------------------------
__global__ void wprep_kernel(const float* __restrict__ ftw,
                             const unsigned char* __restrict__ stm) {
    const int t = threadIdx.x;
    if (blockIdx.x == NCH) {
        __shared__ int fFloat, fBool;
        if (t == 0) { fFloat = 0; fBool = 0; }
        __syncthreads();
        int lf = 0, lb = 0;
        for (int i = t; i < B_SZ; i += 256) {
            unsigned char v = stm[i];
            if (v == 0x80u || v == 0x3fu) lf = 1;
            else if (v != 0u && (i & 3) != 0) lb = 1;
        }
        if (lf) atomicOr(&fFloat, 1);
        if (lb) atomicOr(&fBool, 1);
        __syncthreads();
        if (t == 0) g_mode = fFloat ? 2 : (fBool ? 1 : 0);
        return;
    }
    const int c = blockIdx.x;
    const int n = t >> 1, lh = t & 1;
    const float* src = ftw + (size_t)n * F_SZ;
    unsigned char* dstC = g_wh + (size_t)c * WCHUNK;
#pragma unroll
    for (int s = 0; s < 2; s++) {
        const int kb = c * BK + s * 16 + lh * 8;
        float4 v0 = make_float4(0, 0, 0, 0), v1 = v0;
        if (kb + 4 <= F_SZ) v0 = *(const float4*)(src + kb);
        if (kb + 8 <= F_SZ) v1 = *(const float4*)(src + kb + 4);
        uint4 o;
        o.x = cvtH2(v0.x, v0.y);
        o.y = cvtH2(v0.z, v0.w);
        o.z = cvtH2(v1.x, v1.y);
        o.w = cvtH2(v1.z, v1.w);
        *(uint4*)(dstC + s * PL + SWZ(n, lh)) = o;
    }
}

// ---------------------------------------------------------------------------
// Kernel 0c: per-neuron W rowsum (deterministic tree reduce). 128 blocks.
// ---------------------------------------------------------------------------
__global__ void wsum_kernel(const float* __restrict__ ftw) {
    __shared__ float red[256];
    const int n = blockIdx.x;
    float s = 0.0f;
    for (int k = threadIdx.x; k < F_SZ; k += 256) s += ftw[(size_t)n * F_SZ + k];
    red[threadIdx.x] = s;
    __syncthreads();
    for (int st = 128; st; st >>= 1) {
        if (threadIdx.x < st) red[threadIdx.x] += red[threadIdx.x + st];
        __syncthreads();
    }
    if (threadIdx.x == 0) g_wsum[n] = red[0];
}

// ---------------------------------------------------------------------------
// Kernel 1: fp16 1-term FT GEMM on CENTERED A (a = 0.5 + d; 0.5*rowsum folded
// into bias). 256 thr, 8 warps (2m x 4n), 64x32 warp tiles, BK=32 chunks as
// two k16 sub-steps, 3-stage cp.async pipeline, 48KB dyn smem, occ 2.
// ---------------------------------------------------------------------------
__global__ __launch_bounds__(256, 2)
void ft_mma_kernel(const float* __restrict__ white,
                   const float* __restrict__ black,
                   const float* __restrict__ ftb) {
    extern __shared__ char smc[];
    const int t = threadIdx.x;
    const int lane = t & 31, wid = t >> 5;
    const int wm = wid >> 2, wn = wid & 3;
    const int color = blockIdx.y;
    const int row0 = blockIdx.x * 128;
    const float* __restrict__ A = color ? black : white;
    const uint32_t base = smem_u32(smc);

    // loader mapping: thread t -> row t>>1, 16B-half lh = t&1
    const int lrow = t >> 1, lh = t & 1;
    const float* aRow = A + (size_t)(row0 + lrow) * F_SZ;
    const uint32_t aDst = SWZ(lrow, lh);
    const unsigned char* wSrc = g_wh + t * 16;

    float4 aq[2];

    auto ldA = [&](int ch, int s) {
        const int kb = ch * BK + s * 16 + lh * 8;
        aq[0] = (kb + 4 <= F_SZ) ? *(const float4*)(aRow + kb) : make_float4(0, 0, 0, 0);
        aq[1] = (kb + 8 <= F_SZ) ? *(const float4*)(aRow + kb + 4) : make_float4(0, 0, 0, 0);
    };
    auto stsA = [&](int stg, int s) {
        uint4 v;
        v.x = cvtH2(aq[0].x - 0.5f, aq[0].y - 0.5f);
        v.y = cvtH2(aq[0].z - 0.5f, aq[0].w - 0.5f);
        v.z = cvtH2(aq[1].x - 0.5f, aq[1].y - 0.5f);
        v.w = cvtH2(aq[1].z - 0.5f, aq[1].w - 0.5f);
        *(uint4*)(smc + stg * STG_SZ + s * PL + aDst) = v;
    };
    auto cpW = [&](int ch, int stg) {
        const uint32_t db = base + stg * STG_SZ + W_OFF + (uint32_t)(t * 16);
        const unsigned char* s = wSrc + (size_t)ch * WCHUNK;
        asm volatile("cp.async.cg.shared.global [%0], [%1], 16;"
                     :: "r"(db), "l"(s) : "memory");
        asm volatile("cp.async.cg.shared.global [%0], [%1], 16;"
                     :: "r"(db + PL), "l"(s + PL) : "memory");
    };

    // ldmatrix lane offsets
    const uint32_t offA = SWZ(wm * 64 + (lane & 15), lane >> 4);
    const uint32_t offB = SWZ(wn * 32 + ((lane >> 4) << 3) + (lane & 7), (lane >> 3) & 1);

    float acc[4][4][4];
#pragma unroll
    for (int i = 0; i < 4; i++)
#pragma unroll
        for (int j = 0; j < 4; j++)
#pragma unroll
            for (int q = 0; q < 4; q++) acc[i][j][q] = 0.0f;

    // ---- prologue: chunks 0,1 -> stages 0,1
    cpW(0, 0);
    asm volatile("cp.async.commit_group;" ::: "memory");
    ldA(0, 0); stsA(0, 0);
    ldA(0, 1); stsA(0, 1);
    cpW(1, 1);
    asm volatile("cp.async.commit_group;" ::: "memory");
    ldA(1, 0); stsA(1, 0);
    ldA(1, 1); stsA(1, 1);
    asm volatile("cp.async.wait_group 1;" ::: "memory");
    __syncthreads();

    int stg = 0, stg2 = 2;
    for (int c = 0; c < NCH; ++c) {
        const bool more = (c + 2) < NCH;
        if (more) { ldA(c + 2, 0); cpW(c + 2, stg2); }
        asm volatile("cp.async.commit_group;" ::: "memory");

        const uint32_t sb = base + stg * STG_SZ;
#pragma unroll
        for (int s = 0; s < 2; s++) {
            const uint32_t aPl = sb + s * PL;
            const uint32_t wPl = sb + W_OFF + s * PL;
            uint32_t a[4][4], bh[2][4];
#pragma unroll
            for (int mi = 0; mi < 4; mi++) LDSM_X4(a[mi], aPl + offA + mi * 512);
            LDSM_X4(bh[0], wPl + offB);
            LDSM_X4(bh[1], wPl + offB + 512);
#pragma unroll
            for (int mi = 0; mi < 4; mi++)
#pragma unroll
                for (int ni = 0; ni < 4; ni++) {
                    const int q = ni >> 1, r = (ni & 1) * 2;
                    MMA16816(acc[mi][ni], a[mi], bh[q][r], bh[q][r + 1]);
                }
            if (s == 0 && more) { stsA(stg2, 0); ldA(c + 2, 1); }
        }
        if (more) stsA(stg2, 1);

        asm volatile("cp.async.wait_group 1;" ::: "memory");
        __syncthreads();

        if (++stg == 3) stg = 0;
        if (++stg2 == 3) stg2 = 0;
    }

    // ---- epilogue: bias = ftb + 0.5*rowsum, screlu -> g_scratch
    float2 bias[4];
#pragma unroll
    for (int ni = 0; ni < 4; ni++) {
        const int n = wn * 32 + ni * 8 + (lane & 3) * 2;
        float2 b = *(const float2*)(ftb + n);
        float2 ws = *(const float2*)(g_wsum + n);
        bias[ni].x = b.x + 0.5f * ws.x;
        bias[ni].y = b.y + 0.5f * ws.y;
    }
#pragma unroll
    for (int mi = 0; mi < 4; mi++) {
#pragma unroll
        for (int hf = 0; hf < 2; hf++) {
            const int m = wm * 64 + mi * 16 + (lane >> 2) + hf * 8;
            float* dstRow = g_scratch + (size_t)(row0 + m) * 256 + color * 128;
#pragma unroll
            for (int ni = 0; ni < 4; ni++) {
                const int n = wn * 32 + ni * 8 + (lane & 3) * 2;
                float2 o;
                o.x = screlu(acc[mi][ni][hf * 2 + 0] + bias[ni].x);
                o.y = screlu(acc[mi][ni][hf * 2 + 1] + bias[ni].y);
                *(float2*)(dstRow + n) = o;
            }
        }
    }
}

// ---------------------------------------------------------------------------
// Kernel 2: tail MLP. 512 blocks x 8 warps x 4 rows/warp (unchanged).
// ---------------------------------------------------------------------------
__global__ __launch_bounds__(256)
void tail_kernel(const unsigned char* __restrict__ stm,
                 const float* __restrict__ l1w, const float* __restrict__ l1b,
                 const float* __restrict__ l2w, const float* __restrict__ l2b,
                 const float* __restrict__ outw, const float* __restrict__ outb,
                 float* __restrict__ out) {
    __shared__ float l1w_s[32][260];
    __shared__ float xs[8][256];
    __shared__ float x1s[8][32];
    __shared__ float l2wT[32 * 32];
    __shared__ float l1b_s[32], l2b_s[32], outw_s[32];

    const int t = threadIdx.x;
    for (int idx = t; idx < 32 * 256; idx += 256) {
        int i = idx >> 8, k = idx & 255;
        l1w_s[i][k] = l1w[idx];
    }
    for (int idx = t; idx < 32 * 32; idx += 256) {
        int i = idx >> 5, j = idx & 31;
        l2wT[j * 32 + i] = l2w[idx];
    }
    if (t < 32) {
        l1b_s[t] = l1b[t];
        l2b_s[t] = l2b[t];
        outw_s[t] = outw[t];
    }
    __syncthreads();

    const int w = t >> 5;
    const int lane = t & 31;
    const int mode = g_mode;

#pragma unroll 1
    for (int rr = 0; rr < 4; ++rr) {
        const int r = blockIdx.x * 32 + w * 4 + rr;
        bool s;
        if (mode == 2)      s = (((const float*)(const void*)stm)[r] != 0.0f);
        else if (mode == 1) s = (stm[r] != 0u);
        else                s = (((const int*)(const void*)stm)[r] != 0);
        const int rot = s ? 128 : 0;

        const float* src = g_scratch + (size_t)r * 256;
#pragma unroll
        for (int p = 0; p < 2; p++) {
            const int fi = ((lane + 32 * p) * 4 + rot) & 255;
            *(float4*)&xs[w][(lane + 32 * p) * 4] = *(const float4*)(src + fi);
        }
        __syncwarp();

        float o1 = l1b_s[lane];
#pragma unroll 8
        for (int k4 = 0; k4 < 64; k4++) {
            float4 wv = *(const float4*)&l1w_s[lane][k4 * 4];
            float4 xv = *(const float4*)&xs[w][k4 * 4];
            o1 += wv.x * xv.x + wv.y * xv.y + wv.z * xv.z + wv.w * xv.w;
        }
        x1s[w][lane] = screlu(o1);
        __syncwarp();

        float o2 = l2b_s[lane];
#pragma unroll
        for (int j = 0; j < 32; j++)
            o2 += l2wT[j * 32 + lane] * x1s[w][j];

        float v = screlu(o2) * outw_s[lane];
#pragma unroll
        for (int off = 16; off; off >>= 1)
            v += __shfl_xor_sync(0xffffffffu, v, off);
        if (lane == 0) out[r] = v + outb[0];
        __syncwarp();
    }
}

// ---------------------------------------------------------------------------
extern "C" void kernel_launch(void* const* d_in, const int* in_sizes, int n_in,
                              void* d_out, int out_size) {
    const float* white = (const float*)d_in[0];
    const float* black = (const float*)d_in[1];
    const unsigned char* stm = (const unsigned char*)d_in[2];
    const float* ftw  = (const float*)d_in[3];
    const float* ftb  = (const float*)d_in[4];
    const float* l1w  = (const float*)d_in[5];
    const float* l1b  = (const float*)d_in[6];
    const float* l2w  = (const float*)d_in[7];
    const float* l2b  = (const float*)d_in[8];
    const float* outw = (const float*)d_in[9];
    const float* outb = (const float*)d_in[10];
    float* out = (float*)d_out;

    wprep_kernel<<<NCH + 1, 256>>>(ftw, stm);
    wsum_kernel<<<128, 256>>>(ftw);
    ft_mma_kernel<<<dim3(B_SZ / 128, 2), 256, SMEM_DYN>>>(white, black, ftb);
    tail_kernel<<<B_SZ / 32, 256>>>(stm, l1w, l1b, l2w, l2b, outw, outb, out);
}